// round 1
// baseline (speedup 1.0000x reference)
#include <cuda_runtime.h>
#include <math.h>

// Problem constants
#define NROWS   65536      // B*H*W
#define DDIM    256
#define KCODES  1024
#define GAMMA   0.9f
#define BETA    0.25f

// Output layout: ste[16777216], perplexity[1], loss[1], new_codebook[262144]
#define STE_OFF  0
#define PPL_OFF  16777216
#define LOSS_OFF 16777217
#define CB_OFF   16777218

// ---------------- scratch (device globals; no dynamic alloc allowed) ----------------
__device__ float g_cbT[KCODES * DDIM];            // codebook transposed [K][D]
__device__ float g_norm[KCODES];                  // |e_k|^2
__device__ unsigned long long g_best[NROWS];      // packed (score,k) argmax keys
__device__ float g_dwT[KCODES * DDIM];            // dw transposed [K][D]
__device__ float g_cs[KCODES];                    // cluster sizes
__device__ float g_loss;                          // sum of squared residuals
__device__ float g_scs[KCODES];                   // smoothed cluster size

// ---------------- helpers ----------------
__device__ __forceinline__ void fma2(unsigned long long &d, unsigned long long a,
                                     unsigned long long b) {
    asm("fma.rn.f32x2 %0, %1, %2, %0;" : "+l"(d) : "l"(a), "l"(b));
}
__device__ __forceinline__ unsigned long long pack2(float lo, float hi) {
    unsigned long long r;
    asm("mov.b64 %0, {%1, %2};" : "=l"(r) : "f"(lo), "f"(hi));
    return r;
}
__device__ __forceinline__ float2 unpack2(unsigned long long v) {
    float2 r;
    asm("mov.b64 {%0, %1}, %2;" : "=f"(r.x), "=f"(r.y) : "l"(v));
    return r;
}
// monotonic float -> uint key (larger float => larger uint)
__device__ __forceinline__ unsigned int fkey(float f) {
    unsigned int u = __float_as_uint(f);
    return (u & 0x80000000u) ? ~u : (u | 0x80000000u);
}
// pack score + index; maximize score, tie -> smallest k (matches jnp.argmin first-hit)
__device__ __forceinline__ unsigned long long packkey(float s, unsigned int k) {
    return ((unsigned long long)fkey(s) << 32) | (unsigned long long)(0xFFFFFFFFu - k);
}

// ---------------- kernel 0: zero scratch ----------------
__global__ void zero_k() {
    int i = blockIdx.x * blockDim.x + threadIdx.x;   // 262144 threads
    g_dwT[i] = 0.0f;
    if (i < NROWS)  g_best[i] = 0ull;
    if (i < KCODES) g_cs[i] = 0.0f;
    if (i == 0)     g_loss = 0.0f;
}

// ---------------- kernel 1: transpose codebook [D,K] -> [K,D] ----------------
__global__ void transpose_k(const float* __restrict__ cb) {
    __shared__ float tile[32][33];
    int kx = blockIdx.x * 32;
    int dy = blockIdx.y * 32;
    tile[threadIdx.y][threadIdx.x] = cb[(dy + threadIdx.y) * KCODES + kx + threadIdx.x];
    __syncthreads();
    g_cbT[(size_t)(kx + threadIdx.y) * DDIM + dy + threadIdx.x] = tile[threadIdx.x][threadIdx.y];
}

// ---------------- kernel 2: per-code squared norms (one warp per k) ----------------
__global__ void norm_k() {
    int w = (blockIdx.x * blockDim.x + threadIdx.x) >> 5;
    int lane = threadIdx.x & 31;
    if (w >= KCODES) return;
    float s = 0.0f;
    #pragma unroll
    for (int j = 0; j < 8; j++) {
        float v = g_cbT[(size_t)w * DDIM + lane + j * 32];
        s = fmaf(v, v, s);
    }
    #pragma unroll
    for (int off = 16; off > 0; off >>= 1)
        s += __shfl_xor_sync(0xffffffffu, s, off);
    if (lane == 0) g_norm[w] = s;
}

// ---------------- kernel 3: fp32 GEMM (scores) + per-row argmax via atomicMax ----------------
// score[n][k] = 2 * (x_n . e_k) - |e_k|^2   (maximize == minimize distance)
// Tiles: 128(M) x 128(N) x 16(K-inner), 256 threads, 8x8 micro-tile, f32x2 packed FMA.
__global__ __launch_bounds__(256)
void gemm_argmax(const float* __restrict__ A, const float* __restrict__ B) {
    __shared__ float As[2][16][128];
    __shared__ float Bs[2][16][128];

    const int tid = threadIdx.x;
    const int tx = tid & 15;        // column group
    const int ty = tid >> 4;        // row group
    const int bn = blockIdx.x;      // 0..7   (K blocks)
    const int bm = blockIdx.y;      // 0..511 (N-row blocks)

    const float* Ab = A + (size_t)bm * 128 * DDIM;
    const float* Bb = B + bn * 128;

    // A-load: 512 float4 per tile; this thread handles la, la+1
    const int la  = tid * 2;
    const int am0 = la >> 2,       aq0 = la & 3;
    const int am1 = (la + 1) >> 2, aq1 = (la + 1) & 3;
    // B-load: 512 float4 per tile
    const int br0 = la >> 5,       bc0 = la & 31;
    const int br1 = (la + 1) >> 5, bc1 = (la + 1) & 31;

    unsigned long long acc[8][4];
    #pragma unroll
    for (int i = 0; i < 8; i++)
        #pragma unroll
        for (int p = 0; p < 4; p++) acc[i][p] = 0ull;

    float4 ra0, ra1, rb0, rb1;

    #define FETCH(t)                                                              \
        ra0 = *(const float4*)(Ab + (size_t)am0 * DDIM + (t) * 16 + aq0 * 4);     \
        ra1 = *(const float4*)(Ab + (size_t)am1 * DDIM + (t) * 16 + aq1 * 4);     \
        rb0 = *(const float4*)(Bb + (size_t)((t) * 16 + br0) * KCODES + bc0 * 4); \
        rb1 = *(const float4*)(Bb + (size_t)((t) * 16 + br1) * KCODES + bc1 * 4);

    #define STORE(s)                                                   \
        As[s][aq0 * 4 + 0][am0] = ra0.x;                               \
        As[s][aq0 * 4 + 1][am0] = ra0.y;                               \
        As[s][aq0 * 4 + 2][am0] = ra0.z;                               \
        As[s][aq0 * 4 + 3][am0] = ra0.w;                               \
        As[s][aq1 * 4 + 0][am1] = ra1.x;                               \
        As[s][aq1 * 4 + 1][am1] = ra1.y;                               \
        As[s][aq1 * 4 + 2][am1] = ra1.z;                               \
        As[s][aq1 * 4 + 3][am1] = ra1.w;                               \
        *(float4*)&Bs[s][br0][bc0 * 4] = rb0;                          \
        *(float4*)&Bs[s][br1][bc1 * 4] = rb1;

    FETCH(0);
    STORE(0);
    __syncthreads();

    int s = 0;
    for (int t = 0; t < 16; ++t) {
        if (t < 15) { FETCH(t + 1); }
        #pragma unroll
        for (int kk = 0; kk < 16; ++kk) {
            unsigned long long b2[4];
            #pragma unroll
            for (int p = 0; p < 4; p++)
                b2[p] = *(const unsigned long long*)&Bs[s][kk][tx * 2 + p * 32];
            #pragma unroll
            for (int i = 0; i < 8; i++) {
                float a = As[s][kk][ty + i * 16];
                unsigned long long aa = pack2(a, a);
                #pragma unroll
                for (int p = 0; p < 4; p++) fma2(acc[i][p], aa, b2[p]);
            }
        }
        if (t < 15) { STORE(s ^ 1); }
        __syncthreads();
        s ^= 1;
    }
    #undef FETCH
    #undef STORE

    // epilogue: score = 2*acc - |e|^2, per-row argmax, cross-tx reduce, global atomicMax
    float n0[4], n1[4];
    #pragma unroll
    for (int p = 0; p < 4; p++) {
        int c = bn * 128 + tx * 2 + p * 32;
        n0[p] = g_norm[c];
        n1[p] = g_norm[c + 1];
    }
    #pragma unroll
    for (int i = 0; i < 8; i++) {
        unsigned long long key = 0ull;
        #pragma unroll
        for (int p = 0; p < 4; p++) {
            float2 v = unpack2(acc[i][p]);
            unsigned int c = bn * 128 + tx * 2 + p * 32;
            float s0 = fmaf(2.0f, v.x, -n0[p]);
            float s1 = fmaf(2.0f, v.y, -n1[p]);
            unsigned long long k0 = packkey(s0, c);
            unsigned long long k1 = packkey(s1, c + 1);
            if (k0 > key) key = k0;
            if (k1 > key) key = k1;
        }
        #pragma unroll
        for (int off = 8; off > 0; off >>= 1) {
            unsigned long long o = __shfl_xor_sync(0xffffffffu, key, off, 16);
            if (o > key) key = o;
        }
        if (tx == 0)
            atomicMax(&g_best[bm * 128 + ty + i * 16], key);
    }
}

// ---------------- kernel 4: gather quantized, write ste, accumulate dw/cs/loss ----------------
// one warp per row
__global__ void pass2(const float* __restrict__ flat, float* __restrict__ out) {
    int w = (blockIdx.x * blockDim.x + threadIdx.x) >> 5;
    int lane = threadIdx.x & 31;
    if (w >= NROWS) return;
    unsigned long long key = g_best[w];
    unsigned int k = 0xFFFFFFFFu - (unsigned int)(key & 0xFFFFFFFFull);

    const float* x = flat + (size_t)w * DDIM;
    const float* q = g_cbT + (size_t)k * DDIM;
    float* ste = out + STE_OFF + (size_t)w * DDIM;

    float sum = 0.0f;
    #pragma unroll
    for (int j = 0; j < 8; j++) {
        int d = lane + j * 32;
        float xv = x[d];
        float qv = q[d];
        float df = qv - xv;                 // stop_gradient(quantized - inputs)
        ste[d] = xv + df;                   // matches reference rounding
        sum = fmaf(df, df, sum);
        atomicAdd(&g_dwT[(size_t)k * DDIM + d], xv);
    }
    #pragma unroll
    for (int off = 16; off > 0; off >>= 1)
        sum += __shfl_xor_sync(0xffffffffu, sum, off);
    if (lane == 0) {
        atomicAdd(&g_loss, sum);
        atomicAdd(&g_cs[k], 1.0f);
    }
}

// ---------------- kernel 5: cluster-size smoothing, perplexity, loss ----------------
__global__ void finalA(const float* __restrict__ ehc, const int* __restrict__ counter,
                       float* __restrict__ out) {
    __shared__ float red[1024];
    int k = threadIdx.x;
    float bias = 1.0f - powf(GAMMA, (float)(*counter));
    float cs = g_cs[k];
    float avg = (ehc[k] * GAMMA + cs * (1.0f - GAMMA)) / bias;

    red[k] = avg;
    __syncthreads();
    for (int st = 512; st > 0; st >>= 1) {
        if (k < st) red[k] += red[k + st];
        __syncthreads();
    }
    float n = red[0];
    __syncthreads();

    g_scs[k] = (avg + 1e-5f) / (n + (float)KCODES * 1e-5f) * n;

    float p = cs * (1.0f / (float)NROWS);
    red[k] = -p * logf(p + 1e-10f);
    __syncthreads();
    for (int st = 512; st > 0; st >>= 1) {
        if (k < st) red[k] += red[k + st];
        __syncthreads();
    }
    if (k == 0) {
        out[PPL_OFF]  = expf(red[0]);
        out[LOSS_OFF] = BETA * g_loss / (float)((size_t)NROWS * DDIM);
    }
}

// ---------------- kernel 6: new codebook ----------------
__global__ void finalB(const float* __restrict__ edw, const int* __restrict__ counter,
                       float* __restrict__ out) {
    int i = blockIdx.x * blockDim.x + threadIdx.x;   // d*K + k
    int d = i >> 10;
    int k = i & 1023;
    float bias = 1.0f - powf(GAMMA, (float)(*counter));
    float hdw = edw[i] * GAMMA + g_dwT[(size_t)k * DDIM + d] * (1.0f - GAMMA);
    out[CB_OFF + i] = (hdw / bias) / g_scs[k];
}

// ---------------- launch ----------------
extern "C" void kernel_launch(void* const* d_in, const int* in_sizes, int n_in,
                              void* d_out, int out_size) {
    const float* x   = (const float*)d_in[0];   // inputs [B,H,W,D]
    const float* cb  = (const float*)d_in[1];   // codebook [D,K]
    const float* ehc = (const float*)d_in[2];   // ema_hidden_cluster [K]
    const float* edw = (const float*)d_in[3];   // ema_hidden_dw [D,K]
    const int* counter = (const int*)d_in[4];
    float* out = (float*)d_out;

    zero_k<<<KCODES * DDIM / 256, 256>>>();
    transpose_k<<<dim3(KCODES / 32, DDIM / 32), dim3(32, 32)>>>(cb);
    norm_k<<<KCODES * 32 / 256, 256>>>();
    gemm_argmax<<<dim3(KCODES / 128, NROWS / 128), 256>>>(x, cb);
    pass2<<<NROWS * 32 / 256, 256>>>(x, out);
    finalA<<<1, 1024>>>(ehc, counter, out);
    finalB<<<KCODES * DDIM / 256, 256>>>(edw, counter, out);
}

// round 5
// speedup vs baseline: 1.9417x; 1.9417x over previous
#include <cuda_runtime.h>
#include <cuda_bf16.h>
#include <math.h>
#include <stdint.h>

// Problem constants
#define NROWS   65536      // B*H*W
#define DDIM    256
#define KCODES  1024
#define GAMMA   0.9f
#define BETA    0.25f

// Output layout: ste[16777216], perplexity[1], loss[1], new_codebook[262144]
#define STE_OFF  0
#define PPL_OFF  16777216
#define LOSS_OFF 16777217
#define CB_OFF   16777218

// ---------------- scratch (device globals; no dynamic alloc allowed) ----------------
__device__ float g_cbT[KCODES * DDIM];              // codebook transposed [K][D] fp32
__device__ float g_norm[KCODES];                    // |e_k|^2
__device__ float g_dwT[KCODES * DDIM];              // dw transposed [K][D]
__device__ float g_cs[KCODES];                      // cluster sizes
__device__ float g_loss;                            // sum of squared residuals
__device__ float g_scs[KCODES];                     // smoothed cluster size
__device__ __nv_bfloat16 g_Abf[(size_t)NROWS * DDIM];  // inputs bf16 [N][D]
__device__ __nv_bfloat16 g_Bbf[KCODES * DDIM];         // codebook bf16 [K][D]
__device__ float g_cands[NROWS * 8];                // candidate bf16 scores
__device__ int   g_candi[NROWS * 8];                // candidate code indices

// ---------------- PTX helpers (sm_80-class: valid on plain sm_103 target) ----------------
__device__ __forceinline__ uint32_t smem_u32(const void* p) {
    uint32_t a;
    asm("{ .reg .u64 t; cvta.to.shared.u64 t, %1; cvt.u32.u64 %0, t; }" : "=r"(a) : "l"(p));
    return a;
}
__device__ __forceinline__ void ldsm4(uint32_t* r, uint32_t addr) {
    asm volatile("ldmatrix.sync.aligned.m8n8.x4.shared.b16 {%0,%1,%2,%3}, [%4];"
        : "=r"(r[0]), "=r"(r[1]), "=r"(r[2]), "=r"(r[3]) : "r"(addr));
}
__device__ __forceinline__ void ldsm2(uint32_t* r, uint32_t addr) {
    asm volatile("ldmatrix.sync.aligned.m8n8.x2.shared.b16 {%0,%1}, [%2];"
        : "=r"(r[0]), "=r"(r[1]) : "r"(addr));
}
__device__ __forceinline__ void mma16816(float* c, const uint32_t* a, const uint32_t* b) {
    asm volatile(
        "mma.sync.aligned.m16n8k16.row.col.f32.bf16.bf16.f32 "
        "{%0,%1,%2,%3}, {%4,%5,%6,%7}, {%8,%9}, {%0,%1,%2,%3};"
        : "+f"(c[0]), "+f"(c[1]), "+f"(c[2]), "+f"(c[3])
        : "r"(a[0]), "r"(a[1]), "r"(a[2]), "r"(a[3]), "r"(b[0]), "r"(b[1]));
}
__device__ __forceinline__ void cpasync16(uint32_t s, const void* g) {
    asm volatile("cp.async.cg.shared.global [%0], [%1], 16;" :: "r"(s), "l"(g));
}
#define CP_COMMIT asm volatile("cp.async.commit_group;" ::: "memory")
#define CP_WAIT0  asm volatile("cp.async.wait_group 0;" ::: "memory")

// SMEM layout (bytes). A[128][264]bf16, B[2][128][72]bf16, stage[128][132]f32, norm[1024]f32
#define OFF_A     0
#define OFF_B     67584
#define OFF_STAGE 104448
#define OFF_NORM  172032
#define SMEM_BYTES 176128
#define LDA 264
#define LDB 72
#define LDSTG 132

// ---------------- kernel 0: zero scratch ----------------
__global__ void zero_k() {
    int i = blockIdx.x * blockDim.x + threadIdx.x;   // 262144 threads
    g_dwT[i] = 0.0f;
    if (i < KCODES) g_cs[i] = 0.0f;
    if (i == 0)     g_loss = 0.0f;
}

// ---------------- kernel 1: transpose codebook [D,K] -> [K,D] fp32 ----------------
__global__ void transpose_k(const float* __restrict__ cb) {
    __shared__ float tile[32][33];
    int kx = blockIdx.x * 32;
    int dy = blockIdx.y * 32;
    tile[threadIdx.y][threadIdx.x] = cb[(dy + threadIdx.y) * KCODES + kx + threadIdx.x];
    __syncthreads();
    g_cbT[(size_t)(kx + threadIdx.y) * DDIM + dy + threadIdx.x] = tile[threadIdx.x][threadIdx.y];
}

// ---------------- kernel 2: per-code squared norms + bf16 convert of codebook ----------------
__global__ void norm_conv_k() {
    int w = (blockIdx.x * blockDim.x + threadIdx.x) >> 5;
    int lane = threadIdx.x & 31;
    if (w >= KCODES) return;
    float s = 0.0f;
    #pragma unroll
    for (int j = 0; j < 8; j++) {
        int d = lane + j * 32;
        float v = g_cbT[(size_t)w * DDIM + d];
        g_Bbf[(size_t)w * DDIM + d] = __float2bfloat16_rn(v);
        s = fmaf(v, v, s);
    }
    #pragma unroll
    for (int off = 16; off > 0; off >>= 1)
        s += __shfl_xor_sync(0xffffffffu, s, off);
    if (lane == 0) g_norm[w] = s;
}

// ---------------- kernel 3: bf16 convert of inputs ----------------
__global__ void conv_x(const float* __restrict__ x) {
    size_t i = ((size_t)blockIdx.x * 256 + threadIdx.x) * 8;
    float4 v0 = *(const float4*)(x + i);
    float4 v1 = *(const float4*)(x + i + 4);
    union { __nv_bfloat16 h[8]; uint4 u; } o;
    o.h[0] = __float2bfloat16_rn(v0.x); o.h[1] = __float2bfloat16_rn(v0.y);
    o.h[2] = __float2bfloat16_rn(v0.z); o.h[3] = __float2bfloat16_rn(v0.w);
    o.h[4] = __float2bfloat16_rn(v1.x); o.h[5] = __float2bfloat16_rn(v1.y);
    o.h[6] = __float2bfloat16_rn(v1.z); o.h[7] = __float2bfloat16_rn(v1.w);
    *(uint4*)(g_Abf + i) = o.u;
}

// ---------------- kernel 4: HMMA bf16 GEMM + per-row top-4x2 candidates ----------------
// CTA: 128 rows x all 1024 codes. 8 warps (2 x 4). Warp tile 64x32, mma m16n8k16.
// Per 128-code block: accumulate k=256 in 4 cp.async-pipelined 64-k chunks, stage
// scores to smem, 2 threads/row scan disjoint halves keeping top-4 each.
__global__ __launch_bounds__(256, 1) void gemm_hmma() {
    extern __shared__ char smem[];
    __nv_bfloat16* As = (__nv_bfloat16*)(smem + OFF_A);
    float* stage  = (float*)(smem + OFF_STAGE);
    float* s_norm = (float*)(smem + OFF_NORM);
    const uint32_t sA = smem_u32(smem + OFF_A);
    const uint32_t sB = smem_u32(smem + OFF_B);

    const int tid = threadIdx.x;
    const int lane = tid & 31;
    const int wid = tid >> 5;
    const int wm = wid >> 2;            // 0..1 (row half)
    const int wn = wid & 3;             // 0..3 (col quarter)
    const size_t row0 = (size_t)blockIdx.x * 128;

    // load norms
    for (int i = tid; i < KCODES; i += 256) s_norm[i] = g_norm[i];
    // load A tile 128x256 bf16 into padded smem
    #pragma unroll
    for (int j = 0; j < 16; j++) {
        int idx = tid + j * 256;        // 4096 uint4
        int r = idx >> 5, cv = idx & 31;
        uint4 v = *(const uint4*)(g_Abf + (row0 + r) * DDIM + cv * 8);
        *(uint4*)(As + r * LDA + cv * 8) = v;
    }

    // ldmatrix base addresses
    const uint32_t aBase = sA + (((wm * 64 + (lane & 15)) * LDA + 8 * (lane >> 4)) * 2);
    const uint32_t bBase = sB + (((wn * 32 + (lane & 7)) * LDB + 8 * ((lane >> 3) & 1)) * 2);

    float acc[4][4][4];
    float ts[4] = {-1e30f, -1e30f, -1e30f, -1e30f};
    int   ti[4] = {0, 0, 0, 0};
    const int srow = tid >> 1, shalf = tid & 1;

    // prefetch chunk 0
    {
        int bn = 0, kc = 0;
        #pragma unroll
        for (int j = 0; j < 4; j++) {
            int idx = tid + j * 256;    // 1024 uint4
            int n = idx >> 3, cv = idx & 7;
            cpasync16(sB + 0 * 18432 + (n * LDB + cv * 8) * 2,
                      g_Bbf + (size_t)(bn * 128 + n) * DDIM + kc * 64 + cv * 8);
        }
        CP_COMMIT;
    }

    for (int cidx = 0; cidx < 32; cidx++) {
        const int buf = cidx & 1, kc = cidx & 3, bn = cidx >> 2;
        CP_WAIT0;
        __syncthreads();
        if (cidx < 31) {
            int c2 = cidx + 1, bn2 = c2 >> 2, kc2 = c2 & 3, buf2 = c2 & 1;
            #pragma unroll
            for (int j = 0; j < 4; j++) {
                int idx = tid + j * 256;
                int n = idx >> 3, cv = idx & 7;
                cpasync16(sB + buf2 * 18432 + (n * LDB + cv * 8) * 2,
                          g_Bbf + (size_t)(bn2 * 128 + n) * DDIM + kc2 * 64 + cv * 8);
            }
            CP_COMMIT;
        }
        if (kc == 0) {
            #pragma unroll
            for (int mt = 0; mt < 4; mt++)
                #pragma unroll
                for (int nt = 0; nt < 4; nt++)
                    #pragma unroll
                    for (int e = 0; e < 4; e++) acc[mt][nt][e] = 0.0f;
        }
        // compute: 4 k16 steps over this 64-k chunk
        #pragma unroll
        for (int ks = 0; ks < 4; ks++) {
            uint32_t a[4][4], b[4][2];
            #pragma unroll
            for (int mt = 0; mt < 4; mt++)
                ldsm4(a[mt], aBase + (mt * 16 * LDA + kc * 64 + ks * 16) * 2);
            #pragma unroll
            for (int nt = 0; nt < 4; nt++)
                ldsm2(b[nt], bBase + buf * 18432 + (nt * 8 * LDB + ks * 16) * 2);
            #pragma unroll
            for (int mt = 0; mt < 4; mt++)
                #pragma unroll
                for (int nt = 0; nt < 4; nt++)
                    mma16816(acc[mt][nt], a[mt], b[nt]);
        }
        if (kc == 3) {
            __syncthreads();
            // stage c-frags: thread t holds (row t/4 [+8], col 2(t%4) [+1])
            const int fr = wm * 64 + (lane >> 2);
            const int fc = wn * 32 + 2 * (lane & 3);
            #pragma unroll
            for (int mt = 0; mt < 4; mt++)
                #pragma unroll
                for (int nt = 0; nt < 4; nt++) {
                    int r = fr + mt * 16, c = fc + nt * 8;
                    *(float2*)&stage[r * LDSTG + c] =
                        make_float2(acc[mt][nt][0], acc[mt][nt][1]);
                    *(float2*)&stage[(r + 8) * LDSTG + c] =
                        make_float2(acc[mt][nt][2], acc[mt][nt][3]);
                }
            __syncthreads();
            // scan: 2 threads per row, 64 cols each, keep top-4
            #pragma unroll
            for (int j = 0; j < 16; j++) {
                float4 v = *(float4*)&stage[srow * LDSTG + shalf * 64 + j * 4];
                float vs[4] = {v.x, v.y, v.z, v.w};
                #pragma unroll
                for (int e = 0; e < 4; e++) {
                    int col = shalf * 64 + j * 4 + e;
                    int code = bn * 128 + col;
                    float s = fmaf(2.0f, vs[e], -s_norm[code]);
                    if (s > ts[3]) {
                        ts[3] = s; ti[3] = code;
                        if (ts[3] > ts[2]) { float t = ts[2]; ts[2] = ts[3]; ts[3] = t;
                                             int u = ti[2]; ti[2] = ti[3]; ti[3] = u; }
                        if (ts[2] > ts[1]) { float t = ts[1]; ts[1] = ts[2]; ts[2] = t;
                                             int u = ti[1]; ti[1] = ti[2]; ti[2] = u; }
                        if (ts[1] > ts[0]) { float t = ts[0]; ts[0] = ts[1]; ts[1] = t;
                                             int u = ti[0]; ti[0] = ti[1]; ti[1] = u; }
                    }
                }
            }
        }
    }
    // write candidates
    #pragma unroll
    for (int j = 0; j < 4; j++) {
        g_cands[(row0 + srow) * 8 + shalf * 4 + j] = ts[j];
        g_candi[(row0 + srow) * 8 + shalf * 4 + j] = ti[j];
    }
}

// ---------------- kernel 5: exact rescore (R1-identical arithmetic) + outputs ----------------
// one warp per row; lanes 0..7 each rescore one candidate with a single sequential
// fp32 FMA chain over k=0..255 (bit-identical to the R1 passing kernel's scoring),
// then warp-argmax with ties -> lowest code index.
__global__ void pass2(const float* __restrict__ flat, float* __restrict__ out) {
    int w = (blockIdx.x * blockDim.x + threadIdx.x) >> 5;
    int lane = threadIdx.x & 31;
    if (w >= NROWS) return;

    const float* x = flat + (size_t)w * DDIM;

    float s = -1e30f;
    int cand = 0x7FFFFFFF;
    if (lane < 8) {
        cand = g_candi[w * 8 + lane];
        const float4* e4 = (const float4*)(g_cbT + (size_t)cand * DDIM);
        const float4* x4 = (const float4*)x;
        float d = 0.0f;
        #pragma unroll 8
        for (int kb = 0; kb < 64; kb++) {
            float4 ev = e4[kb];
            float4 xv = x4[kb];
            d = fmaf(xv.x, ev.x, d);
            d = fmaf(xv.y, ev.y, d);
            d = fmaf(xv.z, ev.z, d);
            d = fmaf(xv.w, ev.w, d);
        }
        s = fmaf(2.0f, d, -g_norm[cand]);
    }
    // argmax among lanes 0..7, tie -> lower index
    #pragma unroll
    for (int off = 4; off > 0; off >>= 1) {
        float so = __shfl_xor_sync(0xffffffffu, s, off, 8);
        int   co = __shfl_xor_sync(0xffffffffu, cand, off, 8);
        if (so > s || (so == s && co < cand)) { s = so; cand = co; }
    }
    int bk = __shfl_sync(0xffffffffu, cand, 0);

    const float* q = g_cbT + (size_t)bk * DDIM;
    float* ste = out + STE_OFF + (size_t)w * DDIM;
    float sum = 0.0f;
    #pragma unroll
    for (int j = 0; j < 8; j++) {
        int d = lane + j * 32;
        float xv = x[d];
        float qv = q[d];
        float df = qv - xv;
        ste[d] = xv + df;
        sum = fmaf(df, df, sum);
        atomicAdd(&g_dwT[(size_t)bk * DDIM + d], xv);
    }
    #pragma unroll
    for (int off = 16; off > 0; off >>= 1)
        sum += __shfl_xor_sync(0xffffffffu, sum, off);
    if (lane == 0) {
        atomicAdd(&g_loss, sum);
        atomicAdd(&g_cs[bk], 1.0f);
    }
}

// ---------------- kernel 6: cluster-size smoothing, perplexity, loss ----------------
__global__ void finalA(const float* __restrict__ ehc, const int* __restrict__ counter,
                       float* __restrict__ out) {
    __shared__ float red[1024];
    int k = threadIdx.x;
    float bias = 1.0f - powf(GAMMA, (float)(*counter));
    float cs = g_cs[k];
    float avg = (ehc[k] * GAMMA + cs * (1.0f - GAMMA)) / bias;

    red[k] = avg;
    __syncthreads();
    for (int st = 512; st > 0; st >>= 1) {
        if (k < st) red[k] += red[k + st];
        __syncthreads();
    }
    float n = red[0];
    __syncthreads();

    g_scs[k] = (avg + 1e-5f) / (n + (float)KCODES * 1e-5f) * n;

    float p = cs * (1.0f / (float)NROWS);
    red[k] = -p * logf(p + 1e-10f);
    __syncthreads();
    for (int st = 512; st > 0; st >>= 1) {
        if (k < st) red[k] += red[k + st];
        __syncthreads();
    }
    if (k == 0) {
        out[PPL_OFF]  = expf(red[0]);
        out[LOSS_OFF] = BETA * g_loss / (float)((size_t)NROWS * DDIM);
    }
}

// ---------------- kernel 7: new codebook ----------------
__global__ void finalB(const float* __restrict__ edw, const int* __restrict__ counter,
                       float* __restrict__ out) {
    int i = blockIdx.x * blockDim.x + threadIdx.x;   // d*K + k
    int d = i >> 10;
    int k = i & 1023;
    float bias = 1.0f - powf(GAMMA, (float)(*counter));
    float hdw = edw[i] * GAMMA + g_dwT[(size_t)k * DDIM + d] * (1.0f - GAMMA);
    out[CB_OFF + i] = (hdw / bias) / g_scs[k];
}

// ---------------- launch ----------------
extern "C" void kernel_launch(void* const* d_in, const int* in_sizes, int n_in,
                              void* d_out, int out_size) {
    const float* x   = (const float*)d_in[0];   // inputs [B,H,W,D]
    const float* cb  = (const float*)d_in[1];   // codebook [D,K]
    const float* ehc = (const float*)d_in[2];   // ema_hidden_cluster [K]
    const float* edw = (const float*)d_in[3];   // ema_hidden_dw [D,K]
    const int* counter = (const int*)d_in[4];
    float* out = (float*)d_out;

    static int attr_done = 0;
    if (!attr_done) {
        cudaFuncSetAttribute(gemm_hmma, cudaFuncAttributeMaxDynamicSharedMemorySize,
                             SMEM_BYTES);
        attr_done = 1;
    }

    zero_k<<<KCODES * DDIM / 256, 256>>>();
    transpose_k<<<dim3(KCODES / 32, DDIM / 32), dim3(32, 32)>>>(cb);
    norm_conv_k<<<KCODES * 32 / 256, 256>>>();
    conv_x<<<(int)((size_t)NROWS * DDIM / 8 / 256), 256>>>(x);
    gemm_hmma<<<NROWS / 128, 256, SMEM_BYTES>>>();
    pass2<<<NROWS * 32 / 256, 256>>>(x, out);
    finalA<<<1, 1024>>>(ehc, counter, out);
    finalB<<<KCODES * DDIM / 256, 256>>>(edw, counter, out);
}

// round 6
// speedup vs baseline: 2.5952x; 1.3365x over previous
#include <cuda_runtime.h>
#include <cuda_bf16.h>
#include <math.h>
#include <stdint.h>

// Problem constants
#define NROWS   65536      // B*H*W
#define DDIM    256
#define KCODES  1024
#define GAMMA   0.9f
#define BETA    0.25f

// Output layout: ste[16777216], perplexity[1], loss[1], new_codebook[262144]
#define STE_OFF  0
#define PPL_OFF  16777216
#define LOSS_OFF 16777217
#define CB_OFF   16777218

// ---------------- scratch (device globals; no dynamic alloc allowed) ----------------
__device__ float g_cbT[KCODES * DDIM];              // codebook transposed [K][D] fp32
__device__ float g_norm[KCODES];                    // |e_k|^2
__device__ float g_dwT[KCODES * DDIM];              // dw transposed [K][D]
__device__ float g_cs[KCODES];                      // cluster sizes
__device__ float g_loss;                            // sum of squared residuals
__device__ float g_scs[KCODES];                     // smoothed cluster size
__device__ __nv_bfloat16 g_Bbf[KCODES * DDIM];      // codebook bf16 [K][D]
__device__ int   g_candi[NROWS * 8];                // candidate code indices

// ---------------- PTX helpers (sm_80-class: valid on plain sm_103 target) ----------------
__device__ __forceinline__ uint32_t smem_u32(const void* p) {
    uint32_t a;
    asm("{ .reg .u64 t; cvta.to.shared.u64 t, %1; cvt.u32.u64 %0, t; }" : "=r"(a) : "l"(p));
    return a;
}
__device__ __forceinline__ void ldsm4(uint32_t* r, uint32_t addr) {
    asm volatile("ldmatrix.sync.aligned.m8n8.x4.shared.b16 {%0,%1,%2,%3}, [%4];"
        : "=r"(r[0]), "=r"(r[1]), "=r"(r[2]), "=r"(r[3]) : "r"(addr));
}
__device__ __forceinline__ void ldsm2(uint32_t* r, uint32_t addr) {
    asm volatile("ldmatrix.sync.aligned.m8n8.x2.shared.b16 {%0,%1}, [%2];"
        : "=r"(r[0]), "=r"(r[1]) : "r"(addr));
}
__device__ __forceinline__ void mma16816(float* c, const uint32_t* a, const uint32_t* b) {
    asm volatile(
        "mma.sync.aligned.m16n8k16.row.col.f32.bf16.bf16.f32 "
        "{%0,%1,%2,%3}, {%4,%5,%6,%7}, {%8,%9}, {%0,%1,%2,%3};"
        : "+f"(c[0]), "+f"(c[1]), "+f"(c[2]), "+f"(c[3])
        : "r"(a[0]), "r"(a[1]), "r"(a[2]), "r"(a[3]), "r"(b[0]), "r"(b[1]));
}
__device__ __forceinline__ void cpasync16(uint32_t s, const void* g) {
    asm volatile("cp.async.cg.shared.global [%0], [%1], 16;" :: "r"(s), "l"(g));
}
#define CP_COMMIT asm volatile("cp.async.commit_group;" ::: "memory")
#define CP_WAIT0  asm volatile("cp.async.wait_group 0;" ::: "memory")

// SMEM layout (bytes). A[64][264]bf16, B[2][128][72]bf16, norm[1024]f32
#define OFF_A     0
#define OFF_B     33792
#define OFF_NORM  70656
#define SMEM_BYTES 74752
#define LDA 264
#define LDB 72

// ---------------- kernel 0: zero scratch ----------------
__global__ void zero_k() {
    int i = blockIdx.x * blockDim.x + threadIdx.x;   // 262144 threads
    g_dwT[i] = 0.0f;
    if (i < KCODES) g_cs[i] = 0.0f;
    if (i == 0)     g_loss = 0.0f;
}

// ---------------- kernel 1: transpose codebook [D,K] -> [K,D] fp32 ----------------
__global__ void transpose_k(const float* __restrict__ cb) {
    __shared__ float tile[32][33];
    int kx = blockIdx.x * 32;
    int dy = blockIdx.y * 32;
    tile[threadIdx.y][threadIdx.x] = cb[(dy + threadIdx.y) * KCODES + kx + threadIdx.x];
    __syncthreads();
    g_cbT[(size_t)(kx + threadIdx.y) * DDIM + dy + threadIdx.x] = tile[threadIdx.x][threadIdx.y];
}

// ---------------- kernel 2: per-code squared norms + bf16 convert of codebook ----------------
__global__ void norm_conv_k() {
    int w = (blockIdx.x * blockDim.x + threadIdx.x) >> 5;
    int lane = threadIdx.x & 31;
    if (w >= KCODES) return;
    float s = 0.0f;
    #pragma unroll
    for (int j = 0; j < 8; j++) {
        int d = lane + j * 32;
        float v = g_cbT[(size_t)w * DDIM + d];
        g_Bbf[(size_t)w * DDIM + d] = __float2bfloat16_rn(v);
        s = fmaf(v, v, s);
    }
    #pragma unroll
    for (int off = 16; off > 0; off >>= 1)
        s += __shfl_xor_sync(0xffffffffu, s, off);
    if (lane == 0) g_norm[w] = s;
}

// ---------------- kernel 3: HMMA bf16 GEMM + fragment-resident top-2/quarter ----------------
// CTA: 64 rows x all 1024 codes. 8 warps (2 row-halves x 4 col-quarters), warp tile
// 32x32, mma m16n8k16. A loaded fp32 from x and converted to bf16 in-kernel.
// Per thread: running top-2 per owned fragment row; 4-lane shuffle merge at the end
// gives top-2 per 256-code quarter -> 8 candidates/row in g_candi.
__global__ __launch_bounds__(256, 2) void gemm_hmma(const float* __restrict__ x) {
    extern __shared__ char smem[];
    __nv_bfloat16* As = (__nv_bfloat16*)(smem + OFF_A);
    float* s_norm = (float*)(smem + OFF_NORM);
    const uint32_t sA = smem_u32(smem + OFF_A);
    const uint32_t sB = smem_u32(smem + OFF_B);

    const int tid = threadIdx.x;
    const int lane = tid & 31;
    const int wid = tid >> 5;
    const int wm = wid >> 2;            // 0..1 (32-row half)
    const int wn = wid & 3;             // 0..3 (32-col quarter of each 128 block)
    const size_t row0 = (size_t)blockIdx.x * 64;

    // prefetch B chunk 0 early (overlaps A convert)
    #pragma unroll
    for (int j = 0; j < 4; j++) {
        int idx = tid + j * 256;        // 1024 uint4
        int n = idx >> 3, cv = idx & 7;
        cpasync16(sB + (n * LDB + cv * 8) * 2,
                  g_Bbf + (size_t)n * DDIM + cv * 8);
    }
    CP_COMMIT;

    // load norms
    for (int i = tid; i < KCODES; i += 256) s_norm[i] = g_norm[i];
    // load A tile 64x256 fp32 -> bf16 smem (padded)
    #pragma unroll
    for (int j = 0; j < 16; j++) {
        int idx = tid + j * 256;        // 4096 float4
        int r = idx >> 6, cv = idx & 63;
        float4 v = *(const float4*)(x + (row0 + r) * DDIM + cv * 4);
        union { __nv_bfloat16 h[4]; uint2 u; } o;
        o.h[0] = __float2bfloat16_rn(v.x); o.h[1] = __float2bfloat16_rn(v.y);
        o.h[2] = __float2bfloat16_rn(v.z); o.h[3] = __float2bfloat16_rn(v.w);
        *(uint2*)(As + r * LDA + cv * 4) = o.u;
    }

    // ldmatrix base addresses
    const uint32_t aBase = sA + (((wm * 32 + (lane & 15)) * LDA + 8 * (lane >> 4)) * 2);
    const uint32_t bBase = sB + (((wn * 32 + (lane & 7)) * LDB + 8 * ((lane >> 3) & 1)) * 2);

    float acc[2][4][4];
    // running top-2 per owned fragment row (4 rows per thread)
    float ts0[4], ts1[4];
    int   ti0[4], ti1[4];
    #pragma unroll
    for (int r = 0; r < 4; r++) {
        ts0[r] = -1e30f; ts1[r] = -1e30f; ti0[r] = 0; ti1[r] = 0;
    }

    for (int cidx = 0; cidx < 32; cidx++) {
        const int buf = cidx & 1, kc = cidx & 3, bn = cidx >> 2;
        CP_WAIT0;
        __syncthreads();
        if (cidx < 31) {
            int c2 = cidx + 1, bn2 = c2 >> 2, kc2 = c2 & 3, buf2 = c2 & 1;
            #pragma unroll
            for (int j = 0; j < 4; j++) {
                int idx = tid + j * 256;
                int n = idx >> 3, cv = idx & 7;
                cpasync16(sB + buf2 * 18432 + (n * LDB + cv * 8) * 2,
                          g_Bbf + (size_t)(bn2 * 128 + n) * DDIM + kc2 * 64 + cv * 8);
            }
            CP_COMMIT;
        }
        if (kc == 0) {
            #pragma unroll
            for (int mt = 0; mt < 2; mt++)
                #pragma unroll
                for (int nt = 0; nt < 4; nt++)
                    #pragma unroll
                    for (int e = 0; e < 4; e++) acc[mt][nt][e] = 0.0f;
        }
        // compute: 4 k16 steps over this 64-k chunk
        #pragma unroll
        for (int ks = 0; ks < 4; ks++) {
            uint32_t a[2][4], b[4][2];
            #pragma unroll
            for (int mt = 0; mt < 2; mt++)
                ldsm4(a[mt], aBase + (mt * 16 * LDA + kc * 64 + ks * 16) * 2);
            #pragma unroll
            for (int nt = 0; nt < 4; nt++)
                ldsm2(b[nt], bBase + buf * 18432 + (nt * 8 * LDB + ks * 16) * 2);
            #pragma unroll
            for (int mt = 0; mt < 2; mt++)
                #pragma unroll
                for (int nt = 0; nt < 4; nt++)
                    mma16816(acc[mt][nt], a[mt], b[nt]);
        }
        if (kc == 3) {
            // fold this block's scores into per-row running top-2
            const int cbase = bn * 128 + wn * 32 + 2 * (lane & 3);
            #pragma unroll
            for (int mt = 0; mt < 2; mt++)
                #pragma unroll
                for (int e = 0; e < 4; e++) {
                    const int rr = mt * 2 + (e >> 1);
                    #pragma unroll
                    for (int nt = 0; nt < 4; nt++) {
                        int code = cbase + nt * 8 + (e & 1);
                        float s = fmaf(2.0f, acc[mt][nt][e], -s_norm[code]);
                        if (s > ts1[rr]) {
                            if (s > ts0[rr]) {
                                ts1[rr] = ts0[rr]; ti1[rr] = ti0[rr];
                                ts0[rr] = s;       ti0[rr] = code;
                            } else {
                                ts1[rr] = s;       ti1[rr] = code;
                            }
                        }
                    }
                }
        }
    }

    // merge top-2 across the 4 lanes sharing each row (lane groups of 4)
    #pragma unroll
    for (int rr = 0; rr < 4; rr++) {
        #pragma unroll
        for (int off = 1; off < 4; off <<= 1) {
            float o0 = __shfl_xor_sync(0xffffffffu, ts0[rr], off, 4);
            int   oi0 = __shfl_xor_sync(0xffffffffu, ti0[rr], off, 4);
            float o1 = __shfl_xor_sync(0xffffffffu, ts1[rr], off, 4);
            int   oi1 = __shfl_xor_sync(0xffffffffu, ti1[rr], off, 4);
            if (o0 > ts0[rr]) {
                if (o1 > ts0[rr]) { ts1[rr] = o1;      ti1[rr] = oi1; }
                else              { ts1[rr] = ts0[rr]; ti1[rr] = ti0[rr]; }
                ts0[rr] = o0; ti0[rr] = oi0;
            } else if (o0 > ts1[rr]) {
                ts1[rr] = o0; ti1[rr] = oi0;
            }
        }
    }
    if ((lane & 3) == 0) {
        const int g = lane >> 2;
        #pragma unroll
        for (int rr = 0; rr < 4; rr++) {
            int row = wm * 32 + (rr >> 1) * 16 + (rr & 1) * 8 + g;
            g_candi[(row0 + row) * 8 + wn * 2 + 0] = ti0[rr];
            g_candi[(row0 + row) * 8 + wn * 2 + 1] = ti1[rr];
        }
    }
}

// ---------------- kernel 4: exact rescore (R1-identical arithmetic) + outputs ----------------
// one warp per row; lanes 0..7 each rescore one candidate with a single sequential
// fp32 FMA chain over k=0..255, then warp-argmax with ties -> lowest code index.
__global__ void pass2(const float* __restrict__ flat, float* __restrict__ out) {
    int w = (blockIdx.x * blockDim.x + threadIdx.x) >> 5;
    int lane = threadIdx.x & 31;
    if (w >= NROWS) return;

    const float* x = flat + (size_t)w * DDIM;

    float s = -1e30f;
    int cand = 0x7FFFFFFF;
    if (lane < 8) {
        cand = g_candi[w * 8 + lane];
        const float4* e4 = (const float4*)(g_cbT + (size_t)cand * DDIM);
        const float4* x4 = (const float4*)x;
        float d = 0.0f;
        #pragma unroll 8
        for (int kb = 0; kb < 64; kb++) {
            float4 ev = e4[kb];
            float4 xv = x4[kb];
            d = fmaf(xv.x, ev.x, d);
            d = fmaf(xv.y, ev.y, d);
            d = fmaf(xv.z, ev.z, d);
            d = fmaf(xv.w, ev.w, d);
        }
        s = fmaf(2.0f, d, -g_norm[cand]);
    }
    // argmax among lanes 0..7, tie -> lower index
    #pragma unroll
    for (int off = 4; off > 0; off >>= 1) {
        float so = __shfl_xor_sync(0xffffffffu, s, off, 8);
        int   co = __shfl_xor_sync(0xffffffffu, cand, off, 8);
        if (so > s || (so == s && co < cand)) { s = so; cand = co; }
    }
    int bk = __shfl_sync(0xffffffffu, cand, 0);

    const float* q = g_cbT + (size_t)bk * DDIM;
    float* ste = out + STE_OFF + (size_t)w * DDIM;
    float sum = 0.0f;
    #pragma unroll
    for (int j = 0; j < 8; j++) {
        int d = lane + j * 32;
        float xv = x[d];
        float qv = q[d];
        float df = qv - xv;
        ste[d] = xv + df;
        sum = fmaf(df, df, sum);
        atomicAdd(&g_dwT[(size_t)bk * DDIM + d], xv);
    }
    #pragma unroll
    for (int off = 16; off > 0; off >>= 1)
        sum += __shfl_xor_sync(0xffffffffu, sum, off);
    if (lane == 0) {
        atomicAdd(&g_loss, sum);
        atomicAdd(&g_cs[bk], 1.0f);
    }
}

// ---------------- kernel 5: cluster-size smoothing, perplexity, loss ----------------
__global__ void finalA(const float* __restrict__ ehc, const int* __restrict__ counter,
                       float* __restrict__ out) {
    __shared__ float red[1024];
    int k = threadIdx.x;
    float bias = 1.0f - powf(GAMMA, (float)(*counter));
    float cs = g_cs[k];
    float avg = (ehc[k] * GAMMA + cs * (1.0f - GAMMA)) / bias;

    red[k] = avg;
    __syncthreads();
    for (int st = 512; st > 0; st >>= 1) {
        if (k < st) red[k] += red[k + st];
        __syncthreads();
    }
    float n = red[0];
    __syncthreads();

    g_scs[k] = (avg + 1e-5f) / (n + (float)KCODES * 1e-5f) * n;

    float p = cs * (1.0f / (float)NROWS);
    red[k] = -p * logf(p + 1e-10f);
    __syncthreads();
    for (int st = 512; st > 0; st >>= 1) {
        if (k < st) red[k] += red[k + st];
        __syncthreads();
    }
    if (k == 0) {
        out[PPL_OFF]  = expf(red[0]);
        out[LOSS_OFF] = BETA * g_loss / (float)((size_t)NROWS * DDIM);
    }
}

// ---------------- kernel 6: new codebook ----------------
__global__ void finalB(const float* __restrict__ edw, const int* __restrict__ counter,
                       float* __restrict__ out) {
    int i = blockIdx.x * blockDim.x + threadIdx.x;   // d*K + k
    int d = i >> 10;
    int k = i & 1023;
    float bias = 1.0f - powf(GAMMA, (float)(*counter));
    float hdw = edw[i] * GAMMA + g_dwT[(size_t)k * DDIM + d] * (1.0f - GAMMA);
    out[CB_OFF + i] = (hdw / bias) / g_scs[k];
}

// ---------------- launch ----------------
extern "C" void kernel_launch(void* const* d_in, const int* in_sizes, int n_in,
                              void* d_out, int out_size) {
    const float* x   = (const float*)d_in[0];   // inputs [B,H,W,D]
    const float* cb  = (const float*)d_in[1];   // codebook [D,K]
    const float* ehc = (const float*)d_in[2];   // ema_hidden_cluster [K]
    const float* edw = (const float*)d_in[3];   // ema_hidden_dw [D,K]
    const int* counter = (const int*)d_in[4];
    float* out = (float*)d_out;

    static int attr_done = 0;
    if (!attr_done) {
        cudaFuncSetAttribute(gemm_hmma, cudaFuncAttributeMaxDynamicSharedMemorySize,
                             SMEM_BYTES);
        attr_done = 1;
    }

    zero_k<<<KCODES * DDIM / 256, 256>>>();
    transpose_k<<<dim3(KCODES / 32, DDIM / 32), dim3(32, 32)>>>(cb);
    norm_conv_k<<<KCODES * 32 / 256, 256>>>();
    gemm_hmma<<<NROWS / 64, 256, SMEM_BYTES>>>(x);
    pass2<<<NROWS * 32 / 256, 256>>>(x, out);
    finalA<<<1, 1024>>>(ehc, counter, out);
    finalB<<<KCODES * DDIM / 256, 256>>>(edw, counter, out);
}